// round 15
// baseline (speedup 1.0000x reference)
#include <cuda_runtime.h>

#define LSEQ 512
#define BSZ 1024
#define NTAG 64
#define START_TAG 62
#define END_TAG 63
#define GB 8   // batches per group (mma N dimension)

// ---- tf32 helpers ----
__device__ __forceinline__ unsigned to_tf32(float f) {
    unsigned r;
    asm("cvt.rna.tf32.f32 %0, %1;" : "=r"(r) : "f"(f));
    return r;
}
__device__ __forceinline__ void mma8(float& d0, float& d1, float& d2, float& d3,
                                     unsigned a0, unsigned a1, unsigned a2,
                                     unsigned a3, unsigned b0, unsigned b1) {
    asm("mma.sync.aligned.m16n8k8.row.col.f32.tf32.tf32.f32 "
        "{%0,%1,%2,%3}, {%4,%5,%6,%7}, {%8,%9}, {%0,%1,%2,%3};"
        : "+f"(d0), "+f"(d1), "+f"(d2), "+f"(d3)
        : "r"(a0), "r"(a1), "r"(a2), "r"(a3), "r"(b0), "r"(b1));
}

// ============================================================================
// Tensor-core CRF kernel, M-SPLIT x4, LEAN (no hi/lo compensation).
// Block = 128 threads (4 warps) = one group of 8 batches; grid = 128.
// Warp w owns output rows [16w,16w+16); E A-fragments constant in 32 regs.
//
// vs R14: (a) lo-compensation chain removed (R13/R14 measured rel_err 7e-7;
// error budget shows plain tf32 V rounding lands ~1e-4 << 1e-3) -- halves
// mma count and removes 16 cvt + 16 sub from the per-step chain (the
// measured alu=17.4%); (b) V stored in SMEM already tf32-rounded, so the
// B-fragment LDS feeds mma directly (producer-side 4 cvt replaces
// consumer-side 16; numerically identical); (c) prefetch rings deepened to
// distance 4 (step is now ~300cyc, distance 2 would re-expose DRAM lat);
// (d) unroll 2 to stop I$ thrash.
//
// Numerics otherwise identical to R13/R14: linear-domain v'=(E@v)*exp(f)*s,
// per-column renorm every 4 steps, deferred (maxw at l%4==3, consumed as
// 1/hi + c+=log(hi) at next l%4==0; preinit 1.0; no exit obligation);
// mask-keep from registers (myn holds f32 v').
// Fragment maps (m16n8k8 tf32): A a0..a3=(g,i)(g+8,i)(g,i+4)(g+8,i+4);
// B b0,b1=(i,g)(i+4,g); D c0..c3=(g,2i)(g,2i+1)(g+8,2i)(g+8,2i+1);
// g=lane>>2, i=lane&3.
// ============================================================================
__global__ void __launch_bounds__(128) crf_mma_kernel(
    const float* __restrict__ feats,
    const int*   __restrict__ tags,
    const float* __restrict__ mask,
    const float* __restrict__ transition,
    float* __restrict__ out)
{
    __shared__ __align__(16) float V[2][NTAG * GB];  // tf32-rounded values
    __shared__ float maxw[4][GB];
    __shared__ float endb[4][GB];
    __shared__ float apb[GB];

    const int tid  = threadIdx.x;
    const int w    = tid >> 5;
    const int lane = tid & 31;
    const int gID  = lane >> 2;
    const int tig  = lane & 3;
    const int bG   = blockIdx.x * GB;
    const int g0   = 2 * tig, g1 = g0 + 1;      // D columns owned
    const int R0   = 16 * w + gID, R1 = R0 + 8; // D rows owned

    // ---- E fragments (constant) ----
    unsigned A[8][4];
#pragma unroll
    for (int kt = 0; kt < 8; ++kt) {
        const int C0 = 8 * kt + tig, C1 = C0 + 4;
        A[kt][0] = to_tf32(__expf(__ldg(transition + R0 * NTAG + C0)));
        A[kt][1] = to_tf32(__expf(__ldg(transition + R1 * NTAG + C0)));
        A[kt][2] = to_tf32(__expf(__ldg(transition + R0 * NTAG + C1)));
        A[kt][3] = to_tf32(__expf(__ldg(transition + R1 * NTAG + C1)));
    }

    // ---- V0 = one-hot(START) (exact in tf32) ----
    for (int i = tid; i < NTAG * GB; i += 128)
        V[0][i] = ((i >> 3) == START_TAG) ? 1.0f : 0.0f;
    if (tid < 32) ((float*)maxw)[tid] = 1.0f;   // first renorm-consume no-op

    float cc0 = 0.0f, cc1 = 0.0f;   // log-offsets for columns g0, g1
    float myn[4];                   // f32 v' at (R0,g0)(R0,g1)(R1,g0)(R1,g1)
    myn[0] = myn[1] = (R0 == START_TAG) ? 1.0f : 0.0f;
    myn[2] = myn[3] = (R1 == START_TAG) ? 1.0f : 0.0f;

    // ---- prefetch rings (distance 4): 4 feat scalars + mask pair ----
    float  fr[4][4];
    float2 mrr[4];
#pragma unroll
    for (int p = 0; p < 4; ++p) {
        fr[p][0] = __ldg(feats + ((size_t)p * BSZ + bG + g0) * NTAG + R0);
        fr[p][1] = __ldg(feats + ((size_t)p * BSZ + bG + g1) * NTAG + R0);
        fr[p][2] = __ldg(feats + ((size_t)p * BSZ + bG + g0) * NTAG + R1);
        fr[p][3] = __ldg(feats + ((size_t)p * BSZ + bG + g1) * NTAG + R1);
        mrr[p] = *(const float2*)(mask + (size_t)p * BSZ + bG + g0);
    }
    __syncthreads();

#pragma unroll 2
    for (int l = 0; l < LSEQ; ++l) {
        const int u = l & 3;
        const float f0 = fr[l & 3][0], f1 = fr[l & 3][1];
        const float f2 = fr[l & 3][2], f3 = fr[l & 3][3];
        const float2 mm = mrr[l & 3];
        {   // refill rings (distance 4)
            int ln = l + 4; if (ln > LSEQ - 1) ln = LSEQ - 1;
            fr[l & 3][0] = __ldg(feats + ((size_t)ln * BSZ + bG + g0) * NTAG + R0);
            fr[l & 3][1] = __ldg(feats + ((size_t)ln * BSZ + bG + g1) * NTAG + R0);
            fr[l & 3][2] = __ldg(feats + ((size_t)ln * BSZ + bG + g0) * NTAG + R1);
            fr[l & 3][3] = __ldg(feats + ((size_t)ln * BSZ + bG + g1) * NTAG + R1);
            mrr[l & 3] = *(const float2*)(mask + (size_t)ln * BSZ + bG + g0);
        }

        // consume deferred renorm (every 4th step), per column
        float scale0 = 1.0f, scale1 = 1.0f;
        if (u == 0) {
            const float h0 = fmaxf(fmaxf(maxw[0][g0], maxw[1][g0]),
                                   fmaxf(maxw[2][g0], maxw[3][g0]));
            const float h1 = fmaxf(fmaxf(maxw[0][g1], maxw[1][g1]),
                                   fmaxf(maxw[2][g1], maxw[3][g1]));
            scale0 = __fdividef(1.0f, h0);  cc0 += __logf(h0);
            scale1 = __fdividef(1.0f, h1);  cc1 += __logf(h1);
        }

        // ---- B fragments: 16 LDS.32, already tf32 -> feed mma directly ----
        const float* Vo = V[l & 1];
        unsigned vB[16];
#pragma unroll
        for (int kt = 0; kt < 8; ++kt) {
            vB[2 * kt]     = __float_as_uint(Vo[(8 * kt + tig) * GB + gID]);
            vB[2 * kt + 1] = __float_as_uint(Vo[(8 * kt + tig + 4) * GB + gID]);
        }

        // ---- D = E @ V : 2 parallel chains of depth 4 ----
        float da[4] = {0,0,0,0}, db[4] = {0,0,0,0};
#pragma unroll
        for (int kt = 0; kt < 4; ++kt)
            mma8(da[0], da[1], da[2], da[3],
                 A[kt][0], A[kt][1], A[kt][2], A[kt][3],
                 vB[2 * kt], vB[2 * kt + 1]);
#pragma unroll
        for (int kt = 4; kt < 8; ++kt)
            mma8(db[0], db[1], db[2], db[3],
                 A[kt][0], A[kt][1], A[kt][2], A[kt][3],
                 vB[2 * kt], vB[2 * kt + 1]);

        // ---- epilogue: v' = D * exp(feat) * scale; mask-keep from regs ----
        float n0 = (da[0] + db[0]) * (__expf(f0) * scale0);
        float n1 = (da[1] + db[1]) * (__expf(f1) * scale1);
        float n2 = (da[2] + db[2]) * (__expf(f2) * scale0);
        float n3 = (da[3] + db[3]) * (__expf(f3) * scale1);
        if (mm.x == 0.0f) { n0 = myn[0] * scale0; n2 = myn[2] * scale0; }
        if (mm.y == 0.0f) { n1 = myn[1] * scale1; n3 = myn[3] * scale1; }
        myn[0] = n0; myn[1] = n1; myn[2] = n2; myn[3] = n3;

        // store tf32-rounded copy for next step's mma
        float* Vn = V[(l & 1) ^ 1];
        *(float2*)&Vn[R0 * GB + g0] =
            make_float2(__uint_as_float(to_tf32(n0)), __uint_as_float(to_tf32(n1)));
        *(float2*)&Vn[R1 * GB + g0] =
            make_float2(__uint_as_float(to_tf32(n2)), __uint_as_float(to_tf32(n3)));

        if (u == 3) {   // produce next renorm factors (per-column max)
            float lm0 = fmaxf(n0, n2), lm1 = fmaxf(n1, n3);
            lm0 = fmaxf(lm0, __shfl_xor_sync(0xffffffffu, lm0, 4));
            lm0 = fmaxf(lm0, __shfl_xor_sync(0xffffffffu, lm0, 8));
            lm0 = fmaxf(lm0, __shfl_xor_sync(0xffffffffu, lm0, 16));
            lm1 = fmaxf(lm1, __shfl_xor_sync(0xffffffffu, lm1, 4));
            lm1 = fmaxf(lm1, __shfl_xor_sync(0xffffffffu, lm1, 8));
            lm1 = fmaxf(lm1, __shfl_xor_sync(0xffffffffu, lm1, 16));
            if (lane < 4) { maxw[w][2 * lane] = lm0; maxw[w][2 * lane + 1] = lm1; }
        }
        __syncthreads();
    }

    // ---- allpath per column: c + log( sum_t v[t]*exp(T[END,t]) ) ----
    {
        const float e0 = __expf(__ldg(transition + END_TAG * NTAG + R0));
        const float e1 = __expf(__ldg(transition + END_TAG * NTAG + R1));
        float s0 = myn[0] * e0 + myn[2] * e1;
        float s1 = myn[1] * e0 + myn[3] * e1;
        s0 += __shfl_xor_sync(0xffffffffu, s0, 4);
        s0 += __shfl_xor_sync(0xffffffffu, s0, 8);
        s0 += __shfl_xor_sync(0xffffffffu, s0, 16);
        s1 += __shfl_xor_sync(0xffffffffu, s1, 4);
        s1 += __shfl_xor_sync(0xffffffffu, s1, 8);
        s1 += __shfl_xor_sync(0xffffffffu, s1, 16);
        if (lane < 4) { endb[w][2 * lane] = s0; endb[w][2 * lane + 1] = s1; }
    }
    __syncthreads();
    if (tid < 4) {   // w==0, tig==tid: owns columns 2*tid, 2*tid+1 (cc0/cc1)
        const int ca = 2 * tid, cb = ca + 1;
        apb[ca] = cc0 + __logf((endb[0][ca] + endb[1][ca]) +
                               (endb[2][ca] + endb[3][ca]));
        apb[cb] = cc1 + __logf((endb[0][cb] + endb[1][cb]) +
                               (endb[2][cb] + endb[3][cb]));
    }

    // ---- realpath: 16 threads per batch, each sums 32 L-positions ----
    const int g   = tid >> 4;
    const int sub = tid & 15;
    const int b   = bG + g;
    float rsum = 0.0f, rlen = 0.0f;
#pragma unroll 4
    for (int i = 0; i < 32; ++i) {
        const int l = sub + 16 * i;
        int tag  = __ldg(tags + l * BSZ + b);
        int prev = (l == 0) ? START_TAG : __ldg(tags + (l - 1) * BSZ + b);
        float m  = __ldg(mask + l * BSZ + b);
        float emit = __ldg(feats + ((size_t)l * BSZ + b) * NTAG + tag);
        float tr   = __ldg(transition + tag * NTAG + prev);
        rsum += (emit + tr) * m;
        rlen += m;
    }
#pragma unroll
    for (int o = 8; o > 0; o >>= 1) {
        rsum += __shfl_xor_sync(0xffffffffu, rsum, o);
        rlen += __shfl_xor_sync(0xffffffffu, rlen, o);
    }
    __syncthreads();

    if (sub == 0) {
        const int length = (int)(rlen + 0.5f);
        const int last = (length > 0) ? __ldg(tags + (length - 1) * BSZ + b)
                                      : START_TAG;
        const float real = rsum + __ldg(transition + END_TAG * NTAG + last);
        out[b] = apb[g] - real;
    }
}

extern "C" void kernel_launch(void* const* d_in, const int* in_sizes, int n_in,
                              void* d_out, int out_size) {
    const float* feats      = (const float*)d_in[0];
    const int*   tags       = (const int*)  d_in[1];
    const float* mask       = (const float*)d_in[2];
    const float* transition = (const float*)d_in[3];
    float* out = (float*)d_out;

    crf_mma_kernel<<<BSZ / GB, 128>>>(feats, tags, mask, transition, out);
}

// round 16
// speedup vs baseline: 1.8740x; 1.8740x over previous
#include <cuda_runtime.h>

#define LSEQ 512
#define BSZ 1024
#define NTAG 64
#define START_TAG 62
#define END_TAG 63
#define GB 8   // batches per group (mma N dimension)

// ---- tf32 helpers ----
__device__ __forceinline__ unsigned to_tf32(float f) {
    unsigned r;
    asm("cvt.rna.tf32.f32 %0, %1;" : "=r"(r) : "f"(f));
    return r;
}
__device__ __forceinline__ void mma8(float& d0, float& d1, float& d2, float& d3,
                                     unsigned a0, unsigned a1, unsigned a2,
                                     unsigned a3, unsigned b0, unsigned b1) {
    asm("mma.sync.aligned.m16n8k8.row.col.f32.tf32.tf32.f32 "
        "{%0,%1,%2,%3}, {%4,%5,%6,%7}, {%8,%9}, {%0,%1,%2,%3};"
        : "+f"(d0), "+f"(d1), "+f"(d2), "+f"(d3)
        : "r"(a0), "r"(a1), "r"(a2), "r"(a3), "r"(b0), "r"(b1));
}

// ============================================================================
// Tensor-core CRF kernel, M-SPLIT x4, LEAN -- REGISTER-RING FIX.
//
// R13-R15 indexed their prefetch rings with runtime values (fr[l&3]), which
// ptxas demotes to LOCAL MEMORY: every step paid serialized LDL/STL round
// trips (the missing ~1000 cyc/step; why R15 got slower with a deeper
// ring, issue=9.7%, regs=72). This round restores R4's proven structure:
// outer loop over l4, fully-unrolled inner u=0..3, so all ring indices and
// the V ping-pong selection (l&1 == u&1) are compile-time constants and the
// rings live in registers.
//
// Math is byte-identical to R15 (verified rel_err 7.8e-7): block = 128
// threads (4 warps) = one group of 8 batches, grid = 128; warp w owns rows
// [16w,16w+16), E A-fragments constant in 32 regs; lean tf32 (no hi/lo
// compensation); V stored tf32-rounded so B-fragment LDS feeds mma
// directly; linear-domain v' = (E@v)*exp(feat)*scale; per-column renorm
// every 4 steps, deferred; mask-keep from registers.
// Fragment maps (m16n8k8 tf32): A a0..a3=(g,i)(g+8,i)(g,i+4)(g+8,i+4);
// B b0,b1=(i,g)(i+4,g); D c0..c3=(g,2i)(g,2i+1)(g+8,2i)(g+8,2i+1);
// g=lane>>2, i=lane&3.
// ============================================================================
__global__ void __launch_bounds__(128) crf_mma_kernel(
    const float* __restrict__ feats,
    const int*   __restrict__ tags,
    const float* __restrict__ mask,
    const float* __restrict__ transition,
    float* __restrict__ out)
{
    __shared__ __align__(16) float V[2][NTAG * GB];  // tf32-rounded values
    __shared__ float maxw[4][GB];
    __shared__ float endb[4][GB];
    __shared__ float apb[GB];

    const int tid  = threadIdx.x;
    const int w    = tid >> 5;
    const int lane = tid & 31;
    const int gID  = lane >> 2;
    const int tig  = lane & 3;
    const int bG   = blockIdx.x * GB;
    const int g0   = 2 * tig, g1 = g0 + 1;      // D columns owned
    const int R0   = 16 * w + gID, R1 = R0 + 8; // D rows owned

    // ---- E fragments (constant) ----
    unsigned A[8][4];
#pragma unroll
    for (int kt = 0; kt < 8; ++kt) {
        const int C0 = 8 * kt + tig, C1 = C0 + 4;
        A[kt][0] = to_tf32(__expf(__ldg(transition + R0 * NTAG + C0)));
        A[kt][1] = to_tf32(__expf(__ldg(transition + R1 * NTAG + C0)));
        A[kt][2] = to_tf32(__expf(__ldg(transition + R0 * NTAG + C1)));
        A[kt][3] = to_tf32(__expf(__ldg(transition + R1 * NTAG + C1)));
    }

    // ---- V0 = one-hot(START) (exact in tf32) ----
    for (int i = tid; i < NTAG * GB; i += 128)
        V[0][i] = ((i >> 3) == START_TAG) ? 1.0f : 0.0f;
    if (tid < 32) ((float*)maxw)[tid] = 1.0f;   // first renorm-consume no-op

    float cc0 = 0.0f, cc1 = 0.0f;   // log-offsets for columns g0, g1
    float myn[4];                   // f32 v' at (R0,g0)(R0,g1)(R1,g0)(R1,g1)
    myn[0] = myn[1] = (R0 == START_TAG) ? 1.0f : 0.0f;
    myn[2] = myn[3] = (R1 == START_TAG) ? 1.0f : 0.0f;

    // ---- prefetch rings (distance 4), CONSTANT-INDEXED ----
    float  fr[4][4];
    float2 mrr[4];
#pragma unroll
    for (int p = 0; p < 4; ++p) {
        fr[p][0] = __ldg(feats + ((size_t)p * BSZ + bG + g0) * NTAG + R0);
        fr[p][1] = __ldg(feats + ((size_t)p * BSZ + bG + g1) * NTAG + R0);
        fr[p][2] = __ldg(feats + ((size_t)p * BSZ + bG + g0) * NTAG + R1);
        fr[p][3] = __ldg(feats + ((size_t)p * BSZ + bG + g1) * NTAG + R1);
        mrr[p] = *(const float2*)(mask + (size_t)p * BSZ + bG + g0);
    }
    __syncthreads();

    for (int l4 = 0; l4 < LSEQ; l4 += 4) {
#pragma unroll
        for (int u = 0; u < 4; ++u) {      // ring index u: compile-time
            const int l = l4 + u;
            const float f0 = fr[u][0], f1 = fr[u][1];
            const float f2 = fr[u][2], f3 = fr[u][3];
            const float2 mm = mrr[u];
            {   // refill rings (distance 4)
                int ln = l + 4; if (ln > LSEQ - 1) ln = LSEQ - 1;
                fr[u][0] = __ldg(feats + ((size_t)ln * BSZ + bG + g0) * NTAG + R0);
                fr[u][1] = __ldg(feats + ((size_t)ln * BSZ + bG + g1) * NTAG + R0);
                fr[u][2] = __ldg(feats + ((size_t)ln * BSZ + bG + g0) * NTAG + R1);
                fr[u][3] = __ldg(feats + ((size_t)ln * BSZ + bG + g1) * NTAG + R1);
                mrr[u] = *(const float2*)(mask + (size_t)ln * BSZ + bG + g0);
            }

            // consume deferred renorm (every 4th step), per column
            float scale0 = 1.0f, scale1 = 1.0f;
            if (u == 0) {
                const float h0 = fmaxf(fmaxf(maxw[0][g0], maxw[1][g0]),
                                       fmaxf(maxw[2][g0], maxw[3][g0]));
                const float h1 = fmaxf(fmaxf(maxw[0][g1], maxw[1][g1]),
                                       fmaxf(maxw[2][g1], maxw[3][g1]));
                scale0 = __fdividef(1.0f, h0);  cc0 += __logf(h0);
                scale1 = __fdividef(1.0f, h1);  cc1 += __logf(h1);
            }

            // ---- B fragments: 16 LDS.32 (tf32 values, feed mma direct) ----
            const float* Vo = V[u & 1];          // compile-time select
            unsigned vB[16];
#pragma unroll
            for (int kt = 0; kt < 8; ++kt) {
                vB[2 * kt]     = __float_as_uint(Vo[(8 * kt + tig) * GB + gID]);
                vB[2 * kt + 1] = __float_as_uint(Vo[(8 * kt + tig + 4) * GB + gID]);
            }

            // ---- D = E @ V : 2 parallel chains of depth 4 ----
            float da[4] = {0, 0, 0, 0}, db[4] = {0, 0, 0, 0};
#pragma unroll
            for (int kt = 0; kt < 4; ++kt)
                mma8(da[0], da[1], da[2], da[3],
                     A[kt][0], A[kt][1], A[kt][2], A[kt][3],
                     vB[2 * kt], vB[2 * kt + 1]);
#pragma unroll
            for (int kt = 4; kt < 8; ++kt)
                mma8(db[0], db[1], db[2], db[3],
                     A[kt][0], A[kt][1], A[kt][2], A[kt][3],
                     vB[2 * kt], vB[2 * kt + 1]);

            // ---- epilogue: v' = D * exp(feat) * scale; mask-keep regs ----
            float n0 = (da[0] + db[0]) * (__expf(f0) * scale0);
            float n1 = (da[1] + db[1]) * (__expf(f1) * scale1);
            float n2 = (da[2] + db[2]) * (__expf(f2) * scale0);
            float n3 = (da[3] + db[3]) * (__expf(f3) * scale1);
            if (mm.x == 0.0f) { n0 = myn[0] * scale0; n2 = myn[2] * scale0; }
            if (mm.y == 0.0f) { n1 = myn[1] * scale1; n3 = myn[3] * scale1; }
            myn[0] = n0; myn[1] = n1; myn[2] = n2; myn[3] = n3;

            // store tf32-rounded copy for next step's mma
            float* Vn = V[(u & 1) ^ 1];          // compile-time select
            *(float2*)&Vn[R0 * GB + g0] = make_float2(
                __uint_as_float(to_tf32(n0)), __uint_as_float(to_tf32(n1)));
            *(float2*)&Vn[R1 * GB + g0] = make_float2(
                __uint_as_float(to_tf32(n2)), __uint_as_float(to_tf32(n3)));

            if (u == 3) {   // produce next renorm factors (per-column max)
                float lm0 = fmaxf(n0, n2), lm1 = fmaxf(n1, n3);
                lm0 = fmaxf(lm0, __shfl_xor_sync(0xffffffffu, lm0, 4));
                lm0 = fmaxf(lm0, __shfl_xor_sync(0xffffffffu, lm0, 8));
                lm0 = fmaxf(lm0, __shfl_xor_sync(0xffffffffu, lm0, 16));
                lm1 = fmaxf(lm1, __shfl_xor_sync(0xffffffffu, lm1, 4));
                lm1 = fmaxf(lm1, __shfl_xor_sync(0xffffffffu, lm1, 8));
                lm1 = fmaxf(lm1, __shfl_xor_sync(0xffffffffu, lm1, 16));
                if (lane < 4) {
                    maxw[w][2 * lane] = lm0;
                    maxw[w][2 * lane + 1] = lm1;
                }
            }
            __syncthreads();
        }
    }

    // ---- allpath per column: c + log( sum_t v[t]*exp(T[END,t]) ) ----
    {
        const float e0 = __expf(__ldg(transition + END_TAG * NTAG + R0));
        const float e1 = __expf(__ldg(transition + END_TAG * NTAG + R1));
        float s0 = myn[0] * e0 + myn[2] * e1;
        float s1 = myn[1] * e0 + myn[3] * e1;
        s0 += __shfl_xor_sync(0xffffffffu, s0, 4);
        s0 += __shfl_xor_sync(0xffffffffu, s0, 8);
        s0 += __shfl_xor_sync(0xffffffffu, s0, 16);
        s1 += __shfl_xor_sync(0xffffffffu, s1, 4);
        s1 += __shfl_xor_sync(0xffffffffu, s1, 8);
        s1 += __shfl_xor_sync(0xffffffffu, s1, 16);
        if (lane < 4) { endb[w][2 * lane] = s0; endb[w][2 * lane + 1] = s1; }
    }
    __syncthreads();
    if (tid < 4) {   // w==0, tig==tid: owns columns 2*tid, 2*tid+1 (cc0/cc1)
        const int ca = 2 * tid, cb = ca + 1;
        apb[ca] = cc0 + __logf((endb[0][ca] + endb[1][ca]) +
                               (endb[2][ca] + endb[3][ca]));
        apb[cb] = cc1 + __logf((endb[0][cb] + endb[1][cb]) +
                               (endb[2][cb] + endb[3][cb]));
    }

    // ---- realpath: 16 threads per batch, each sums 32 L-positions ----
    const int g   = tid >> 4;
    const int sub = tid & 15;
    const int b   = bG + g;
    float rsum = 0.0f, rlen = 0.0f;
#pragma unroll 4
    for (int i = 0; i < 32; ++i) {
        const int l = sub + 16 * i;
        int tag  = __ldg(tags + l * BSZ + b);
        int prev = (l == 0) ? START_TAG : __ldg(tags + (l - 1) * BSZ + b);
        float m  = __ldg(mask + l * BSZ + b);
        float emit = __ldg(feats + ((size_t)l * BSZ + b) * NTAG + tag);
        float tr   = __ldg(transition + tag * NTAG + prev);
        rsum += (emit + tr) * m;
        rlen += m;
    }
#pragma unroll
    for (int o = 8; o > 0; o >>= 1) {
        rsum += __shfl_xor_sync(0xffffffffu, rsum, o);
        rlen += __shfl_xor_sync(0xffffffffu, rlen, o);
    }
    __syncthreads();

    if (sub == 0) {
        const int length = (int)(rlen + 0.5f);
        const int last = (length > 0) ? __ldg(tags + (length - 1) * BSZ + b)
                                      : START_TAG;
        const float real = rsum + __ldg(transition + END_TAG * NTAG + last);
        out[b] = apb[g] - real;
    }
}

extern "C" void kernel_launch(void* const* d_in, const int* in_sizes, int n_in,
                              void* d_out, int out_size) {
    const float* feats      = (const float*)d_in[0];
    const int*   tags       = (const int*)  d_in[1];
    const float* mask       = (const float*)d_in[2];
    const float* transition = (const float*)d_in[3];
    float* out = (float*)d_out;

    crf_mma_kernel<<<BSZ / GB, 128>>>(feats, tags, mask, transition, out);
}

// round 17
// speedup vs baseline: 1.9176x; 1.0233x over previous
#include <cuda_runtime.h>

#define LSEQ 512
#define BSZ 1024
#define NTAG 64
#define START_TAG 62
#define END_TAG 63
#define GB 8   // batches per group (mma N dimension)

// ---- tf32 helpers ----
__device__ __forceinline__ unsigned to_tf32(float f) {
    unsigned r;
    asm("cvt.rna.tf32.f32 %0, %1;" : "=r"(r) : "f"(f));
    return r;
}
__device__ __forceinline__ void mma8(float& d0, float& d1, float& d2, float& d3,
                                     unsigned a0, unsigned a1, unsigned a2,
                                     unsigned a3, unsigned b0, unsigned b1) {
    asm("mma.sync.aligned.m16n8k8.row.col.f32.tf32.tf32.f32 "
        "{%0,%1,%2,%3}, {%4,%5,%6,%7}, {%8,%9}, {%0,%1,%2,%3};"
        : "+f"(d0), "+f"(d1), "+f"(d2), "+f"(d3)
        : "r"(a0), "r"(a1), "r"(a2), "r"(a3), "r"(b0), "r"(b1));
}

// ============================================================================
// Tensor-core CRF kernel, M-SPLIT x4 -- CHAIN-SHORTENED.
//
// Base = R16 (197us, verified): block = 128 threads (4 warps) = one group of
// 8 batches, grid = 128; warp w owns rows [16w,16w+16), E A-fragments
// constant in 32 regs; constant-indexed register rings; linear-domain
// v' = (E@v)*exp(feat)*scale; per-column renorm every 4 steps, deferred;
// mask-keep from registers.
//
// This round shortens the per-step serial chain (the whole cost at
// 1 block/SM, 1 warp/SMSP):
//  (a) mma accumulation split into 4 parallel chains of depth 2 (was 2x4):
//      dependent-HMMA chain halves.
//  (b) cvt.rna before the V store removed -- raw f32 feeds the tf32 mma
//      (HW truncation). Bias ~2^-11/step * 512 steps ~ 0.25 abs on a ~2600
//      allpath -> rel_err ~1e-4 << 1e-3 threshold.
// Fragment maps (m16n8k8 tf32): A a0..a3=(g,i)(g+8,i)(g,i+4)(g+8,i+4);
// B b0,b1=(i,g)(i+4,g); D c0..c3=(g,2i)(g,2i+1)(g+8,2i)(g+8,2i+1);
// g=lane>>2, i=lane&3.
// ============================================================================
__global__ void __launch_bounds__(128) crf_mma_kernel(
    const float* __restrict__ feats,
    const int*   __restrict__ tags,
    const float* __restrict__ mask,
    const float* __restrict__ transition,
    float* __restrict__ out)
{
    __shared__ __align__(16) float V[2][NTAG * GB];
    __shared__ float maxw[4][GB];
    __shared__ float endb[4][GB];
    __shared__ float apb[GB];

    const int tid  = threadIdx.x;
    const int w    = tid >> 5;
    const int lane = tid & 31;
    const int gID  = lane >> 2;
    const int tig  = lane & 3;
    const int bG   = blockIdx.x * GB;
    const int g0   = 2 * tig, g1 = g0 + 1;      // D columns owned
    const int R0   = 16 * w + gID, R1 = R0 + 8; // D rows owned

    // ---- E fragments (constant) ----
    unsigned A[8][4];
#pragma unroll
    for (int kt = 0; kt < 8; ++kt) {
        const int C0 = 8 * kt + tig, C1 = C0 + 4;
        A[kt][0] = to_tf32(__expf(__ldg(transition + R0 * NTAG + C0)));
        A[kt][1] = to_tf32(__expf(__ldg(transition + R1 * NTAG + C0)));
        A[kt][2] = to_tf32(__expf(__ldg(transition + R0 * NTAG + C1)));
        A[kt][3] = to_tf32(__expf(__ldg(transition + R1 * NTAG + C1)));
    }

    // ---- V0 = one-hot(START) ----
    for (int i = tid; i < NTAG * GB; i += 128)
        V[0][i] = ((i >> 3) == START_TAG) ? 1.0f : 0.0f;
    if (tid < 32) ((float*)maxw)[tid] = 1.0f;   // first renorm-consume no-op

    float cc0 = 0.0f, cc1 = 0.0f;   // log-offsets for columns g0, g1
    float myn[4];                   // f32 v' at (R0,g0)(R0,g1)(R1,g0)(R1,g1)
    myn[0] = myn[1] = (R0 == START_TAG) ? 1.0f : 0.0f;
    myn[2] = myn[3] = (R1 == START_TAG) ? 1.0f : 0.0f;

    // ---- prefetch rings (distance 4), CONSTANT-INDEXED ----
    float  fr[4][4];
    float2 mrr[4];
#pragma unroll
    for (int p = 0; p < 4; ++p) {
        fr[p][0] = __ldg(feats + ((size_t)p * BSZ + bG + g0) * NTAG + R0);
        fr[p][1] = __ldg(feats + ((size_t)p * BSZ + bG + g1) * NTAG + R0);
        fr[p][2] = __ldg(feats + ((size_t)p * BSZ + bG + g0) * NTAG + R1);
        fr[p][3] = __ldg(feats + ((size_t)p * BSZ + bG + g1) * NTAG + R1);
        mrr[p] = *(const float2*)(mask + (size_t)p * BSZ + bG + g0);
    }
    __syncthreads();

    for (int l4 = 0; l4 < LSEQ; l4 += 4) {
#pragma unroll
        for (int u = 0; u < 4; ++u) {      // ring index u: compile-time
            const int l = l4 + u;
            const float f0 = fr[u][0], f1 = fr[u][1];
            const float f2 = fr[u][2], f3 = fr[u][3];
            const float2 mm = mrr[u];
            {   // refill rings (distance 4)
                int ln = l + 4; if (ln > LSEQ - 1) ln = LSEQ - 1;
                fr[u][0] = __ldg(feats + ((size_t)ln * BSZ + bG + g0) * NTAG + R0);
                fr[u][1] = __ldg(feats + ((size_t)ln * BSZ + bG + g1) * NTAG + R0);
                fr[u][2] = __ldg(feats + ((size_t)ln * BSZ + bG + g0) * NTAG + R1);
                fr[u][3] = __ldg(feats + ((size_t)ln * BSZ + bG + g1) * NTAG + R1);
                mrr[u] = *(const float2*)(mask + (size_t)ln * BSZ + bG + g0);
            }

            // consume deferred renorm (every 4th step), per column
            float scale0 = 1.0f, scale1 = 1.0f;
            if (u == 0) {
                const float h0 = fmaxf(fmaxf(maxw[0][g0], maxw[1][g0]),
                                       fmaxf(maxw[2][g0], maxw[3][g0]));
                const float h1 = fmaxf(fmaxf(maxw[0][g1], maxw[1][g1]),
                                       fmaxf(maxw[2][g1], maxw[3][g1]));
                scale0 = __fdividef(1.0f, h0);  cc0 += __logf(h0);
                scale1 = __fdividef(1.0f, h1);  cc1 += __logf(h1);
            }

            // ---- B fragments: 16 LDS.32 (f32; mma uses top bits) ----
            const float* Vo = V[u & 1];          // compile-time select
            unsigned vB[16];
#pragma unroll
            for (int kt = 0; kt < 8; ++kt) {
                vB[2 * kt]     = __float_as_uint(Vo[(8 * kt + tig) * GB + gID]);
                vB[2 * kt + 1] = __float_as_uint(Vo[(8 * kt + tig + 4) * GB + gID]);
            }

            // ---- D = E @ V : 4 parallel chains of depth 2 ----
            float dA[4] = {0,0,0,0}, dB[4] = {0,0,0,0};
            float dC[4] = {0,0,0,0}, dD[4] = {0,0,0,0};
#pragma unroll
            for (int kt = 0; kt < 2; ++kt)
                mma8(dA[0], dA[1], dA[2], dA[3],
                     A[kt][0], A[kt][1], A[kt][2], A[kt][3],
                     vB[2 * kt], vB[2 * kt + 1]);
#pragma unroll
            for (int kt = 2; kt < 4; ++kt)
                mma8(dB[0], dB[1], dB[2], dB[3],
                     A[kt][0], A[kt][1], A[kt][2], A[kt][3],
                     vB[2 * kt], vB[2 * kt + 1]);
#pragma unroll
            for (int kt = 4; kt < 6; ++kt)
                mma8(dC[0], dC[1], dC[2], dC[3],
                     A[kt][0], A[kt][1], A[kt][2], A[kt][3],
                     vB[2 * kt], vB[2 * kt + 1]);
#pragma unroll
            for (int kt = 6; kt < 8; ++kt)
                mma8(dD[0], dD[1], dD[2], dD[3],
                     A[kt][0], A[kt][1], A[kt][2], A[kt][3],
                     vB[2 * kt], vB[2 * kt + 1]);

            // ---- epilogue: v' = D * exp(feat) * scale; mask-keep regs ----
            float n0 = ((dA[0] + dB[0]) + (dC[0] + dD[0])) * (__expf(f0) * scale0);
            float n1 = ((dA[1] + dB[1]) + (dC[1] + dD[1])) * (__expf(f1) * scale1);
            float n2 = ((dA[2] + dB[2]) + (dC[2] + dD[2])) * (__expf(f2) * scale0);
            float n3 = ((dA[3] + dB[3]) + (dC[3] + dD[3])) * (__expf(f3) * scale1);
            if (mm.x == 0.0f) { n0 = myn[0] * scale0; n2 = myn[2] * scale0; }
            if (mm.y == 0.0f) { n1 = myn[1] * scale1; n3 = myn[3] * scale1; }
            myn[0] = n0; myn[1] = n1; myn[2] = n2; myn[3] = n3;

            // store raw f32 (HW tf32-truncates on the next mma)
            float* Vn = V[(u & 1) ^ 1];          // compile-time select
            *(float2*)&Vn[R0 * GB + g0] = make_float2(n0, n1);
            *(float2*)&Vn[R1 * GB + g0] = make_float2(n2, n3);

            if (u == 3) {   // produce next renorm factors (per-column max)
                float lm0 = fmaxf(n0, n2), lm1 = fmaxf(n1, n3);
                lm0 = fmaxf(lm0, __shfl_xor_sync(0xffffffffu, lm0, 4));
                lm0 = fmaxf(lm0, __shfl_xor_sync(0xffffffffu, lm0, 8));
                lm0 = fmaxf(lm0, __shfl_xor_sync(0xffffffffu, lm0, 16));
                lm1 = fmaxf(lm1, __shfl_xor_sync(0xffffffffu, lm1, 4));
                lm1 = fmaxf(lm1, __shfl_xor_sync(0xffffffffu, lm1, 8));
                lm1 = fmaxf(lm1, __shfl_xor_sync(0xffffffffu, lm1, 16));
                if (lane < 4) {
                    maxw[w][2 * lane] = lm0;
                    maxw[w][2 * lane + 1] = lm1;
                }
            }
            __syncthreads();
        }
    }

    // ---- allpath per column: c + log( sum_t v[t]*exp(T[END,t]) ) ----
    {
        const float e0 = __expf(__ldg(transition + END_TAG * NTAG + R0));
        const float e1 = __expf(__ldg(transition + END_TAG * NTAG + R1));
        float s0 = myn[0] * e0 + myn[2] * e1;
        float s1 = myn[1] * e0 + myn[3] * e1;
        s0 += __shfl_xor_sync(0xffffffffu, s0, 4);
        s0 += __shfl_xor_sync(0xffffffffu, s0, 8);
        s0 += __shfl_xor_sync(0xffffffffu, s0, 16);
        s1 += __shfl_xor_sync(0xffffffffu, s1, 4);
        s1 += __shfl_xor_sync(0xffffffffu, s1, 8);
        s1 += __shfl_xor_sync(0xffffffffu, s1, 16);
        if (lane < 4) { endb[w][2 * lane] = s0; endb[w][2 * lane + 1] = s1; }
    }
    __syncthreads();
    if (tid < 4) {   // w==0, tig==tid: owns columns 2*tid, 2*tid+1 (cc0/cc1)
        const int ca = 2 * tid, cb = ca + 1;
        apb[ca] = cc0 + __logf((endb[0][ca] + endb[1][ca]) +
                               (endb[2][ca] + endb[3][ca]));
        apb[cb] = cc1 + __logf((endb[0][cb] + endb[1][cb]) +
                               (endb[2][cb] + endb[3][cb]));
    }

    // ---- realpath: 16 threads per batch, each sums 32 L-positions ----
    const int g   = tid >> 4;
    const int sub = tid & 15;
    const int b   = bG + g;
    float rsum = 0.0f, rlen = 0.0f;
#pragma unroll 4
    for (int i = 0; i < 32; ++i) {
        const int l = sub + 16 * i;
        int tag  = __ldg(tags + l * BSZ + b);
        int prev = (l == 0) ? START_TAG : __ldg(tags + (l - 1) * BSZ + b);
        float m  = __ldg(mask + l * BSZ + b);
        float emit = __ldg(feats + ((size_t)l * BSZ + b) * NTAG + tag);
        float tr   = __ldg(transition + tag * NTAG + prev);
        rsum += (emit + tr) * m;
        rlen += m;
    }
#pragma unroll
    for (int o = 8; o > 0; o >>= 1) {
        rsum += __shfl_xor_sync(0xffffffffu, rsum, o);
        rlen += __shfl_xor_sync(0xffffffffu, rlen, o);
    }
    __syncthreads();

    if (sub == 0) {
        const int length = (int)(rlen + 0.5f);
        const int last = (length > 0) ? __ldg(tags + (length - 1) * BSZ + b)
                                      : START_TAG;
        const float real = rsum + __ldg(transition + END_TAG * NTAG + last);
        out[b] = apb[g] - real;
    }
}

extern "C" void kernel_launch(void* const* d_in, const int* in_sizes, int n_in,
                              void* d_out, int out_size) {
    const float* feats      = (const float*)d_in[0];
    const int*   tags       = (const int*)  d_in[1];
    const float* mask       = (const float*)d_in[2];
    const float* transition = (const float*)d_in[3];
    float* out = (float*)d_out;

    crf_mma_kernel<<<BSZ / GB, 128>>>(feats, tags, mask, transition, out);
}